// round 10
// baseline (speedup 1.0000x reference)
#include <cuda_runtime.h>
#include <cuda_bf16.h>
#include <stdint.h>
#include <math.h>

#define BS   8
#define RES  128
#define NQ   (RES*RES)       // 16384
#define CCH  128
#define NH   8
#define NP   4
#define NTOT (BS*NQ)         // 131072

// ---------------- scratch (device globals; no allocation) -------------------
__device__ float g_value  [(size_t)NTOT*CCH];
__device__ float g_off    [(size_t)NTOT*64];
__device__ float g_attn   [(size_t)NTOT*32];

// packed transposed bf16 weight images, [n][k] row-major, k contiguous
__device__ __align__(16) __nv_bfloat16 g_w1_hi[128*128];  // Wv^T
__device__ __align__(16) __nv_bfloat16 g_w1_lo[128*128];
__device__ __align__(16) __nv_bfloat16 g_w2_hi[96*128];   // [Woff|Wattn]^T
__device__ __align__(16) __nv_bfloat16 g_w3_hi[128*128];  // Wout^T
__device__ __align__(16) __nv_bfloat16 g_w3_lo[128*128];

// ---------------- helpers ---------------------------------------------------
__device__ __forceinline__ uint32_t smem_u32(const void* p) {
    uint32_t a;
    asm("{ .reg .u64 t; cvta.to.shared.u64 t, %1; cvt.u32.u64 %0, t; }" : "=r"(a) : "l"(p));
    return a;
}
__device__ __forceinline__ uint32_t packbf(float a, float b) {
    uint32_t r;
    asm("cvt.rn.bf16x2.f32 %0, %1, %2;" : "=r"(r) : "f"(b), "f"(a));
    return r;
}
// split float4 (4 consecutive k) into hi/lo bf16x2 pairs
__device__ __forceinline__ void split4(float4 v, uint2& hi, uint2& lo) {
    uint32_t h01 = packbf(v.x, v.y);
    uint32_t h23 = packbf(v.z, v.w);
    float f0 = __uint_as_float(h01 << 16);
    float f1 = __uint_as_float(h01 & 0xffff0000u);
    float f2 = __uint_as_float(h23 << 16);
    float f3 = __uint_as_float(h23 & 0xffff0000u);
    hi = make_uint2(h01, h23);
    lo = make_uint2(packbf(v.x - f0, v.y - f1), packbf(v.z - f2, v.w - f3));
}

// mma.sync m16n8k16 row.col bf16 -> f32 accumulate (in-place)
__device__ __forceinline__ void mma16816(float* c, const uint32_t* a, const uint32_t* b) {
    asm volatile(
        "mma.sync.aligned.m16n8k16.row.col.f32.bf16.bf16.f32 "
        "{%0,%1,%2,%3}, {%4,%5,%6,%7}, {%8,%9}, {%0,%1,%2,%3};"
        : "+f"(c[0]), "+f"(c[1]), "+f"(c[2]), "+f"(c[3])
        : "r"(a[0]), "r"(a[1]), "r"(a[2]), "r"(a[3]), "r"(b[0]), "r"(b[1]));
}

__device__ __forceinline__ void ldsm_x4(uint32_t* r, uint32_t addr) {
    asm volatile("ldmatrix.sync.aligned.m8n8.x4.shared.b16 {%0,%1,%2,%3}, [%4];"
        : "=r"(r[0]), "=r"(r[1]), "=r"(r[2]), "=r"(r[3]) : "r"(addr));
}

#define PSTR 136              // padded bf16 row stride (272 bytes, conflict-free)
#define RB   (PSTR*2u)        // 272

// ---------------------------------------------------------------------------
// prep: transposed, split-bf16 packed weight images
// ---------------------------------------------------------------------------
__global__ void prep_kernel(const float* __restrict__ Wv, const float* __restrict__ Woff,
                            const float* __restrict__ Wattn, const float* __restrict__ Wout)
{
    int i = blockIdx.x * 256 + threadIdx.x;
    if (i < 16384) {
        int k = i >> 7, n = i & 127;
        int o = n * 128 + k;
        {
            float v = Wv[i];
            __nv_bfloat16 h = __float2bfloat16(v);
            g_w1_hi[o] = h;
            g_w1_lo[o] = __float2bfloat16(v - __bfloat162float(h));
        }
        {
            float v = Wout[i];
            __nv_bfloat16 h = __float2bfloat16(v);
            g_w3_hi[o] = h;
            g_w3_lo[o] = __float2bfloat16(v - __bfloat162float(h));
        }
    } else if (i < 16384 + 12288) {
        int j = i - 16384;
        int k = j / 96, n = j - 96 * k;
        float v = (n < 64) ? Woff[k * 64 + n] : Wattn[k * 32 + (n - 64)];
        g_w2_hi[n * 128 + k] = __float2bfloat16(v);
    }
}

// ---------------------------------------------------------------------------
// Kernel 1: proj. CTA tile 128 rows x 224 cols, K=128. 8 warps = 4(M) x 2(N).
// cols 0..127 -> value (3-term), 128..191 -> off (1-term), 192..223 -> attn.
// ---------------------------------------------------------------------------
#define P_AH   0u
#define P_AL   (P_AH + 128u*RB)
#define P_WVH  (P_AL + 128u*RB)
#define P_WVL  (P_WVH + 128u*RB)
#define P_W2   (P_WVL + 128u*RB)
#define PROJ_SMEM (P_W2 + 96u*RB)     // 165376

__global__ __launch_bounds__(256, 1) void proj_kernel(
    const float* __restrict__ query,
    const float* __restrict__ bv, const float* __restrict__ boff,
    const float* __restrict__ battn)
{
    extern __shared__ __align__(16) unsigned char smem[];
    const int tid = threadIdx.x;
    const size_t q0 = (size_t)blockIdx.x * 128;

    // ---- stage A: 128x128 fp32 -> hi/lo bf16, padded rows (4096 float4) ----
    {
        const float4* qsrc = (const float4*)(query + q0 * CCH);
        #pragma unroll
        for (int it = 0; it < 16; it++) {
            int idx4 = it * 256 + tid;
            float4 v = qsrc[idx4];
            int row = idx4 >> 5, k0 = (idx4 & 31) << 2;
            uint2 hi, lo; split4(v, hi, lo);
            *(uint2*)(smem + P_AH + row * RB + k0 * 2) = hi;
            *(uint2*)(smem + P_AL + row * RB + k0 * 2) = lo;
        }
    }
    // ---- stage B: copy packed images into padded rows ----
    {
        const uint4* s;
        s = (const uint4*)g_w1_hi;
        #pragma unroll
        for (int it = 0; it < 8; it++) {
            int idx = it * 256 + tid; int row = idx >> 4, seg = idx & 15;
            *(uint4*)(smem + P_WVH + row * RB + seg * 16) = s[idx];
        }
        s = (const uint4*)g_w1_lo;
        #pragma unroll
        for (int it = 0; it < 8; it++) {
            int idx = it * 256 + tid; int row = idx >> 4, seg = idx & 15;
            *(uint4*)(smem + P_WVL + row * RB + seg * 16) = s[idx];
        }
        s = (const uint4*)g_w2_hi;
        #pragma unroll
        for (int it = 0; it < 6; it++) {
            int idx = it * 256 + tid; int row = idx >> 4, seg = idx & 15;
            *(uint4*)(smem + P_W2 + row * RB + seg * 16) = s[idx];
        }
    }
    __syncthreads();

    const int lane = tid & 31, wid = tid >> 5;
    const int wm = wid & 3, wn = wid >> 2;
    const int gr = lane >> 2, tg = lane & 3;
    const uint32_t sb = smem_u32(smem);

    // ldmatrix lane->address precompute
    const uint32_t aoffH = sb + P_AH + (uint32_t)(wm * 32 + (lane & 15)) * RB + ((lane >> 4) << 4);
    const uint32_t aoffL = aoffH + (P_AL - P_AH);
    const uint32_t bRow  = (uint32_t)((lane & 7) + ((lane >> 4 & 1) << 3));
    const uint32_t bCol  = (uint32_t)((lane >> 3 & 1) << 4);
    const uint32_t bvhO  = sb + P_WVH + (uint32_t)(wn * 64) * RB + bRow * RB + bCol;
    const uint32_t bvlO  = bvhO + (P_WVL - P_WVH);
    const uint32_t b2O   = sb + P_W2 + (uint32_t)(wn * 48) * RB + bRow * RB + bCol;

    float accV[8][2][4];
    float accE[6][2][4];
    #pragma unroll
    for (int j = 0; j < 8; j++)
        #pragma unroll
        for (int mt = 0; mt < 2; mt++)
            #pragma unroll
            for (int e = 0; e < 4; e++) accV[j][mt][e] = 0.f;
    #pragma unroll
    for (int j = 0; j < 6; j++)
        #pragma unroll
        for (int mt = 0; mt < 2; mt++)
            #pragma unroll
            for (int e = 0; e < 4; e++) accE[j][mt][e] = 0.f;

    #pragma unroll
    for (int kc = 0; kc < 8; kc++) {
        const uint32_t kOff = (uint32_t)kc * 32;
        uint32_t ah[2][4], al[2][4];
        ldsm_x4(ah[0], aoffH + kOff);
        ldsm_x4(ah[1], aoffH + 16 * RB + kOff);
        ldsm_x4(al[0], aoffL + kOff);
        ldsm_x4(al[1], aoffL + 16 * RB + kOff);
        #pragma unroll
        for (int jp = 0; jp < 4; jp++) {
            uint32_t bh[4], bl[4];
            ldsm_x4(bh, bvhO + (uint32_t)jp * 16 * RB + kOff);
            ldsm_x4(bl, bvlO + (uint32_t)jp * 16 * RB + kOff);
            #pragma unroll
            for (int mt = 0; mt < 2; mt++) {
                mma16816(accV[jp*2][mt],   ah[mt], bh);
                mma16816(accV[jp*2][mt],   ah[mt], bl);
                mma16816(accV[jp*2][mt],   al[mt], bh);
                mma16816(accV[jp*2+1][mt], ah[mt], bh + 2);
                mma16816(accV[jp*2+1][mt], ah[mt], bl + 2);
                mma16816(accV[jp*2+1][mt], al[mt], bh + 2);
            }
        }
        #pragma unroll
        for (int jp = 0; jp < 3; jp++) {
            uint32_t b2[4];
            ldsm_x4(b2, b2O + (uint32_t)jp * 16 * RB + kOff);
            #pragma unroll
            for (int mt = 0; mt < 2; mt++) {
                mma16816(accE[jp*2][mt],   ah[mt], b2);
                mma16816(accE[jp*2+1][mt], ah[mt], b2 + 2);
            }
        }
    }

    __syncthreads();   // all warps done reading smem before attn staging reuse

    // ---- epilogue ----
    const int c0 = tg * 2;
    // value cols
    #pragma unroll
    for (int j = 0; j < 8; j++) {
        int c = wn * 64 + j * 8 + c0;
        float2 b = *(const float2*)(bv + c);
        #pragma unroll
        for (int mt = 0; mt < 2; mt++) {
            #pragma unroll
            for (int hr = 0; hr < 2; hr++) {
                int r = wm * 32 + mt * 16 + gr + hr * 8;
                float2 o = make_float2(accV[j][mt][hr * 2 + 0] + b.x,
                                       accV[j][mt][hr * 2 + 1] + b.y);
                *(float2*)(g_value + (q0 + r) * CCH + c) = o;
            }
        }
    }
    // extra cols (off / attn)
    float* Lst = (float*)(smem + P_AH);   // attn logit staging: [128][32]
    #pragma unroll
    for (int j = 0; j < 6; j++) {
        int ce = 128 + wn * 48 + j * 8 + c0;
        if (ce < 192) {
            float2 b = *(const float2*)(boff + (ce - 128));
            #pragma unroll
            for (int mt = 0; mt < 2; mt++)
                #pragma unroll
                for (int hr = 0; hr < 2; hr++) {
                    int r = wm * 32 + mt * 16 + gr + hr * 8;
                    float2 o = make_float2(accE[j][mt][hr * 2 + 0] + b.x,
                                           accE[j][mt][hr * 2 + 1] + b.y);
                    *(float2*)(g_off + (q0 + r) * 64 + (ce - 128)) = o;
                }
        } else {
            int ca = ce - 192;
            float b0 = battn[ca], b1 = battn[ca + 1];
            #pragma unroll
            for (int mt = 0; mt < 2; mt++)
                #pragma unroll
                for (int hr = 0; hr < 2; hr++) {
                    int r = wm * 32 + mt * 16 + gr + hr * 8;
                    Lst[r * 32 + ca]     = accE[j][mt][hr * 2 + 0] + b0;
                    Lst[r * 32 + ca + 1] = accE[j][mt][hr * 2 + 1] + b1;
                }
        }
    }
    __syncthreads();

    // softmax over P=4 for 128*8 groups
    #pragma unroll
    for (int g = tid; g < 1024; g += 256) {
        int row = g >> 3, h = g & 7;
        float4 l = *(const float4*)(Lst + row * 32 + h * 4);
        float m = fmaxf(fmaxf(l.x, l.y), fmaxf(l.z, l.w));
        float e0 = __expf(l.x - m), e1 = __expf(l.y - m),
              e2 = __expf(l.z - m), e3 = __expf(l.w - m);
        float inv = 1.f / (e0 + e1 + e2 + e3);
        *(float4*)(g_attn + (q0 + row) * 32 + h * 4) =
            make_float4(e0 * inv, e1 * inv, e2 * inv, e3 * inv);
    }
}

// ---------------------------------------------------------------------------
// Kernel 2 (FUSED): bilinear sampling directly into smem A tile (split bf16),
// then out = sampled @ Wout + bout + 2*query. 8 warps = 4(M) x 2(N).
// ---------------------------------------------------------------------------
#define F_AH   0u
#define F_AL   (F_AH + 128u*RB)
#define F_WH   (F_AL + 128u*RB)
#define F_WL   (F_WH + 128u*RB)
#define FUSED_SMEM (F_WL + 128u*RB)   // 139264

__global__ __launch_bounds__(256, 1) void fused_sample_out_kernel(
    const float* __restrict__ bout, const float* __restrict__ query,
    float* __restrict__ out)
{
    extern __shared__ __align__(16) unsigned char smem[];
    const int tid = threadIdx.x;
    const int lane = tid & 31, wid = tid >> 5;
    const size_t q0 = (size_t)blockIdx.x * 128;

    // ---- phase 0: stage Wout hi/lo into padded rows ----
    {
        const uint4* s;
        s = (const uint4*)g_w3_hi;
        #pragma unroll
        for (int it = 0; it < 8; it++) {
            int idx = it * 256 + tid; int row = idx >> 4, seg = idx & 15;
            *(uint4*)(smem + F_WH + row * RB + seg * 16) = s[idx];
        }
        s = (const uint4*)g_w3_lo;
        #pragma unroll
        for (int it = 0; it < 8; it++) {
            int idx = it * 256 + tid; int row = idx >> 4, seg = idx & 15;
            *(uint4*)(smem + F_WL + row * RB + seg * 16) = s[idx];
        }
    }

    // ---- phase 1: bilinear sampling -> split bf16 -> smem A tile ----
    {
        const int h  = lane >> 2;         // head
        const int dq = lane & 3;          // float4 chunk within head
        const int b  = (int)(q0 >> 14);   // batch (CTA covers one batch slice)
        const float* vb = g_value + ((size_t)b * NQ) * CCH + h * 16 + dq * 4;

        #pragma unroll 2
        for (int i = 0; i < 16; i++) {
            const int ql = wid * 16 + i;
            const size_t n = q0 + ql;
            const int q = (int)(n & (NQ - 1));

            const float refx = (float)(q & 127) * (1.0f / 127.0f);
            const float refy = (float)(q >> 7)  * (1.0f / 127.0f);
            const float* off  = g_off  + n * 64 + h * 8;
            const float* attn = g_attn + n * 32 + h * 4;

            float4 acc = make_float4(0.f, 0.f, 0.f, 0.f);
            #pragma unroll
            for (int p = 0; p < NP; p++) {
                float ox = off[p * 2 + 0];
                float oy = off[p * 2 + 1];
                float a  = attn[p];
                float x = (refx + ox * (1.0f / 128.0f)) * 128.0f - 0.5f;
                float y = (refy + oy * (1.0f / 128.0f)) * 128.0f - 0.5f;
                float x0f = floorf(x), y0f = floorf(y);
                int x0 = (int)x0f, y0 = (int)y0f;
                float wx = x - x0f, wy = y - y0f;
                float w00 = (1.f - wx) * (1.f - wy) * a;
                float w10 = wx * (1.f - wy) * a;
                float w01 = (1.f - wx) * wy * a;
                float w11 = wx * wy * a;

                bool xv0 = (unsigned)x0       < 128u;
                bool xv1 = (unsigned)(x0 + 1) < 128u;
                bool yv0 = (unsigned)y0       < 128u;
                bool yv1 = (unsigned)(y0 + 1) < 128u;

                if (yv0) {
                    const float* rp = vb + (size_t)(y0 * 128) * CCH;
                    if (xv0) { float4 v = *(const float4*)(rp + (size_t)x0 * CCH);
                               acc.x += w00 * v.x; acc.y += w00 * v.y; acc.z += w00 * v.z; acc.w += w00 * v.w; }
                    if (xv1) { float4 v = *(const float4*)(rp + (size_t)(x0 + 1) * CCH);
                               acc.x += w10 * v.x; acc.y += w10 * v.y; acc.z += w10 * v.z; acc.w += w10 * v.w; }
                }
                if (yv1) {
                    const float* rp = vb + (size_t)((y0 + 1) * 128) * CCH;
                    if (xv0) { float4 v = *(const float4*)(rp + (size_t)x0 * CCH);
                               acc.x += w01 * v.x; acc.y += w01 * v.y; acc.z += w01 * v.z; acc.w += w01 * v.w; }
                    if (xv1) { float4 v = *(const float4*)(rp + (size_t)(x0 + 1) * CCH);
                               acc.x += w11 * v.x; acc.y += w11 * v.y; acc.z += w11 * v.z; acc.w += w11 * v.w; }
                }
            }

            uint2 hi, lo; split4(acc, hi, lo);
            *(uint2*)(smem + F_AH + ql * RB + lane * 8) = hi;   // k0 = lane*4
            *(uint2*)(smem + F_AL + ql * RB + lane * 8) = lo;
        }
    }
    __syncthreads();

    // ---- phase 2: GEMM with ldmatrix fragments ----
    const int wm = wid & 3, wn = wid >> 2;
    const int gr = lane >> 2, tg = lane & 3;
    const uint32_t sb = smem_u32(smem);

    const uint32_t aoffH = sb + F_AH + (uint32_t)(wm * 32 + (lane & 15)) * RB + ((lane >> 4) << 4);
    const uint32_t aoffL = aoffH + (F_AL - F_AH);
    const uint32_t bRow  = (uint32_t)((lane & 7) + ((lane >> 4 & 1) << 3));
    const uint32_t bCol  = (uint32_t)((lane >> 3 & 1) << 4);
    const uint32_t bhO   = sb + F_WH + (uint32_t)(wn * 64) * RB + bRow * RB + bCol;
    const uint32_t blO   = bhO + (F_WL - F_WH);

    float acc[8][2][4];
    #pragma unroll
    for (int j = 0; j < 8; j++)
        #pragma unroll
        for (int mt = 0; mt < 2; mt++)
            #pragma unroll
            for (int e = 0; e < 4; e++) acc[j][mt][e] = 0.f;

    #pragma unroll
    for (int kc = 0; kc < 8; kc++) {
        const uint32_t kOff = (uint32_t)kc * 32;
        uint32_t ah[2][4], al[2][4];
        ldsm_x4(ah[0], aoffH + kOff);
        ldsm_x4(ah[1], aoffH + 16 * RB + kOff);
        ldsm_x4(al[0], aoffL + kOff);
        ldsm_x4(al[1], aoffL + 16 * RB + kOff);
        #pragma unroll
        for (int jp = 0; jp < 4; jp++) {
            uint32_t bh[4], bl[4];
            ldsm_x4(bh, bhO + (uint32_t)jp * 16 * RB + kOff);
            ldsm_x4(bl, blO + (uint32_t)jp * 16 * RB + kOff);
            #pragma unroll
            for (int mt = 0; mt < 2; mt++) {
                mma16816(acc[jp*2][mt],   ah[mt], bh);
                mma16816(acc[jp*2][mt],   ah[mt], bl);
                mma16816(acc[jp*2][mt],   al[mt], bh);
                mma16816(acc[jp*2+1][mt], ah[mt], bh + 2);
                mma16816(acc[jp*2+1][mt], ah[mt], bl + 2);
                mma16816(acc[jp*2+1][mt], al[mt], bh + 2);
            }
        }
    }

    // ---- epilogue: + bout + 2*query ----
    const int c0 = tg * 2;
    #pragma unroll
    for (int j = 0; j < 8; j++) {
        int c = wn * 64 + j * 8 + c0;
        float2 b = *(const float2*)(bout + c);
        #pragma unroll
        for (int mt = 0; mt < 2; mt++) {
            #pragma unroll
            for (int hr = 0; hr < 2; hr++) {
                int r = wm * 32 + mt * 16 + gr + hr * 8;
                size_t nn = q0 + r;
                float2 qv = *(const float2*)(query + nn * CCH + c);
                float2 o = make_float2(acc[j][mt][hr * 2 + 0] + b.x + 2.0f * qv.x,
                                       acc[j][mt][hr * 2 + 1] + b.y + 2.0f * qv.y);
                *(float2*)(out + nn * CCH + c) = o;
            }
        }
    }
}

// ---------------------------------------------------------------------------
extern "C" void kernel_launch(void* const* d_in, const int* in_sizes, int n_in,
                              void* d_out, int out_size)
{
    const float* query = (const float*)d_in[0];
    const float* Wv    = (const float*)d_in[1];
    const float* bv    = (const float*)d_in[2];
    const float* Woff  = (const float*)d_in[3];
    const float* boff  = (const float*)d_in[4];
    const float* Wattn = (const float*)d_in[5];
    const float* battn = (const float*)d_in[6];
    const float* Wout  = (const float*)d_in[7];
    const float* bout  = (const float*)d_in[8];
    float* out = (float*)d_out;

    cudaFuncSetAttribute(proj_kernel, cudaFuncAttributeMaxDynamicSharedMemorySize, PROJ_SMEM);
    cudaFuncSetAttribute(fused_sample_out_kernel, cudaFuncAttributeMaxDynamicSharedMemorySize, FUSED_SMEM);

    prep_kernel<<<112, 256>>>(Wv, Woff, Wattn, Wout);
    proj_kernel<<<NTOT / 128, 256, PROJ_SMEM>>>(query, bv, boff, battn);
    fused_sample_out_kernel<<<NTOT / 128, 256, FUSED_SMEM>>>(bout, query, out);
}

// round 11
// speedup vs baseline: 2.1199x; 2.1199x over previous
#include <cuda_runtime.h>
#include <cuda_bf16.h>
#include <stdint.h>
#include <math.h>

#define BS   8
#define RES  128
#define NQ   (RES*RES)       // 16384
#define CCH  128
#define NH   8
#define NP   4
#define NTOT (BS*NQ)         // 131072

// ---------------- scratch (device globals; no allocation) -------------------
__device__ float g_value  [(size_t)NTOT*CCH];
__device__ float g_off    [(size_t)NTOT*64];
__device__ float g_attn   [(size_t)NTOT*32];
__device__ float g_sampled[(size_t)NTOT*CCH];

// packed transposed bf16 weight images, [n][k] row-major, k contiguous
__device__ __align__(16) __nv_bfloat16 g_w1_hi[128*128];  // Wv^T
__device__ __align__(16) __nv_bfloat16 g_w1_lo[128*128];
__device__ __align__(16) __nv_bfloat16 g_w2_hi[96*128];   // [Woff|Wattn]^T
__device__ __align__(16) __nv_bfloat16 g_w3_hi[128*128];  // Wout^T
__device__ __align__(16) __nv_bfloat16 g_w3_lo[128*128];

// ---------------- helpers ---------------------------------------------------
__device__ __forceinline__ uint32_t smem_u32(const void* p) {
    uint32_t a;
    asm("{ .reg .u64 t; cvta.to.shared.u64 t, %1; cvt.u32.u64 %0, t; }" : "=r"(a) : "l"(p));
    return a;
}
__device__ __forceinline__ uint32_t packbf(float a, float b) {
    uint32_t r;
    asm("cvt.rn.bf16x2.f32 %0, %1, %2;" : "=r"(r) : "f"(b), "f"(a));
    return r;
}
// split float4 (4 consecutive k) into hi/lo bf16x2 pairs
__device__ __forceinline__ void split4(float4 v, uint2& hi, uint2& lo) {
    uint32_t h01 = packbf(v.x, v.y);
    uint32_t h23 = packbf(v.z, v.w);
    float f0 = __uint_as_float(h01 << 16);
    float f1 = __uint_as_float(h01 & 0xffff0000u);
    float f2 = __uint_as_float(h23 << 16);
    float f3 = __uint_as_float(h23 & 0xffff0000u);
    hi = make_uint2(h01, h23);
    lo = make_uint2(packbf(v.x - f0, v.y - f1), packbf(v.z - f2, v.w - f3));
}

// mma.sync m16n8k16 row.col bf16 -> f32 accumulate (in-place)
__device__ __forceinline__ void mma16816(float* c, const uint32_t* a, const uint32_t* b) {
    asm volatile(
        "mma.sync.aligned.m16n8k16.row.col.f32.bf16.bf16.f32 "
        "{%0,%1,%2,%3}, {%4,%5,%6,%7}, {%8,%9}, {%0,%1,%2,%3};"
        : "+f"(c[0]), "+f"(c[1]), "+f"(c[2]), "+f"(c[3])
        : "r"(a[0]), "r"(a[1]), "r"(a[2]), "r"(a[3]), "r"(b[0]), "r"(b[1]));
}

__device__ __forceinline__ void ldsm_x4(uint32_t* r, uint32_t addr) {
    asm volatile("ldmatrix.sync.aligned.m8n8.x4.shared.b16 {%0,%1,%2,%3}, [%4];"
        : "=r"(r[0]), "=r"(r[1]), "=r"(r[2]), "=r"(r[3]) : "r"(addr));
}

#define PSTR 136              // padded bf16 row stride (272 bytes, conflict-free)
#define RB   (PSTR*2u)        // 272

// ---------------------------------------------------------------------------
// prep: transposed, split-bf16 packed weight images
// ---------------------------------------------------------------------------
__global__ void prep_kernel(const float* __restrict__ Wv, const float* __restrict__ Woff,
                            const float* __restrict__ Wattn, const float* __restrict__ Wout)
{
    int i = blockIdx.x * 256 + threadIdx.x;
    if (i < 16384) {
        int k = i >> 7, n = i & 127;
        int o = n * 128 + k;
        {
            float v = Wv[i];
            __nv_bfloat16 h = __float2bfloat16(v);
            g_w1_hi[o] = h;
            g_w1_lo[o] = __float2bfloat16(v - __bfloat162float(h));
        }
        {
            float v = Wout[i];
            __nv_bfloat16 h = __float2bfloat16(v);
            g_w3_hi[o] = h;
            g_w3_lo[o] = __float2bfloat16(v - __bfloat162float(h));
        }
    } else if (i < 16384 + 12288) {
        int j = i - 16384;
        int k = j / 96, n = j - 96 * k;
        float v = (n < 64) ? Woff[k * 64 + n] : Wattn[k * 32 + (n - 64)];
        g_w2_hi[n * 128 + k] = __float2bfloat16(v);
    }
}

// ---------------------------------------------------------------------------
// Kernel 1: proj. CTA tile 128 rows x 224 cols, K=128. 8 warps = 4(M) x 2(N).
// cols 0..127 -> value (3-term), 128..191 -> off (1-term), 192..223 -> attn.
// ---------------------------------------------------------------------------
#define P_AH   0u
#define P_AL   (P_AH + 128u*RB)
#define P_WVH  (P_AL + 128u*RB)
#define P_WVL  (P_WVH + 128u*RB)
#define P_W2   (P_WVL + 128u*RB)
#define PROJ_SMEM (P_W2 + 96u*RB)     // 165376

__global__ __launch_bounds__(256, 1) void proj_kernel(
    const float* __restrict__ query,
    const float* __restrict__ bv, const float* __restrict__ boff,
    const float* __restrict__ battn)
{
    extern __shared__ __align__(16) unsigned char smem[];
    const int tid = threadIdx.x;
    const size_t q0 = (size_t)blockIdx.x * 128;

    // ---- stage A: 128x128 fp32 -> hi/lo bf16, padded rows (4096 float4) ----
    {
        const float4* qsrc = (const float4*)(query + q0 * CCH);
        #pragma unroll
        for (int it = 0; it < 16; it++) {
            int idx4 = it * 256 + tid;
            float4 v = qsrc[idx4];
            int row = idx4 >> 5, k0 = (idx4 & 31) << 2;
            uint2 hi, lo; split4(v, hi, lo);
            *(uint2*)(smem + P_AH + row * RB + k0 * 2) = hi;
            *(uint2*)(smem + P_AL + row * RB + k0 * 2) = lo;
        }
    }
    // ---- stage B: copy packed images into padded rows ----
    {
        const uint4* s;
        s = (const uint4*)g_w1_hi;
        #pragma unroll
        for (int it = 0; it < 8; it++) {
            int idx = it * 256 + tid; int row = idx >> 4, seg = idx & 15;
            *(uint4*)(smem + P_WVH + row * RB + seg * 16) = s[idx];
        }
        s = (const uint4*)g_w1_lo;
        #pragma unroll
        for (int it = 0; it < 8; it++) {
            int idx = it * 256 + tid; int row = idx >> 4, seg = idx & 15;
            *(uint4*)(smem + P_WVL + row * RB + seg * 16) = s[idx];
        }
        s = (const uint4*)g_w2_hi;
        #pragma unroll
        for (int it = 0; it < 6; it++) {
            int idx = it * 256 + tid; int row = idx >> 4, seg = idx & 15;
            *(uint4*)(smem + P_W2 + row * RB + seg * 16) = s[idx];
        }
    }
    __syncthreads();

    const int lane = tid & 31, wid = tid >> 5;
    const int wm = wid & 3, wn = wid >> 2;
    const int gr = lane >> 2, tg = lane & 3;
    const uint32_t sb = smem_u32(smem);

    // ldmatrix lane->address precompute
    const uint32_t aoffH = sb + P_AH + (uint32_t)(wm * 32 + (lane & 15)) * RB + ((lane >> 4) << 4);
    const uint32_t aoffL = aoffH + (P_AL - P_AH);
    const uint32_t bRow  = (uint32_t)((lane & 7) + ((lane >> 4 & 1) << 3));
    const uint32_t bCol  = (uint32_t)((lane >> 3 & 1) << 4);
    const uint32_t bvhO  = sb + P_WVH + (uint32_t)(wn * 64) * RB + bRow * RB + bCol;
    const uint32_t bvlO  = bvhO + (P_WVL - P_WVH);
    const uint32_t b2O   = sb + P_W2 + (uint32_t)(wn * 48) * RB + bRow * RB + bCol;

    float accV[8][2][4];
    float accE[6][2][4];
    #pragma unroll
    for (int j = 0; j < 8; j++)
        #pragma unroll
        for (int mt = 0; mt < 2; mt++)
            #pragma unroll
            for (int e = 0; e < 4; e++) accV[j][mt][e] = 0.f;
    #pragma unroll
    for (int j = 0; j < 6; j++)
        #pragma unroll
        for (int mt = 0; mt < 2; mt++)
            #pragma unroll
            for (int e = 0; e < 4; e++) accE[j][mt][e] = 0.f;

    #pragma unroll
    for (int kc = 0; kc < 8; kc++) {
        const uint32_t kOff = (uint32_t)kc * 32;
        uint32_t ah[2][4], al[2][4];
        ldsm_x4(ah[0], aoffH + kOff);
        ldsm_x4(ah[1], aoffH + 16 * RB + kOff);
        ldsm_x4(al[0], aoffL + kOff);
        ldsm_x4(al[1], aoffL + 16 * RB + kOff);
        #pragma unroll
        for (int jp = 0; jp < 4; jp++) {
            uint32_t bh[4], bl[4];
            ldsm_x4(bh, bvhO + (uint32_t)jp * 16 * RB + kOff);
            ldsm_x4(bl, bvlO + (uint32_t)jp * 16 * RB + kOff);
            #pragma unroll
            for (int mt = 0; mt < 2; mt++) {
                mma16816(accV[jp*2][mt],   ah[mt], bh);
                mma16816(accV[jp*2][mt],   ah[mt], bl);
                mma16816(accV[jp*2][mt],   al[mt], bh);
                mma16816(accV[jp*2+1][mt], ah[mt], bh + 2);
                mma16816(accV[jp*2+1][mt], ah[mt], bl + 2);
                mma16816(accV[jp*2+1][mt], al[mt], bh + 2);
            }
        }
        #pragma unroll
        for (int jp = 0; jp < 3; jp++) {
            uint32_t b2[4];
            ldsm_x4(b2, b2O + (uint32_t)jp * 16 * RB + kOff);
            #pragma unroll
            for (int mt = 0; mt < 2; mt++) {
                mma16816(accE[jp*2][mt],   ah[mt], b2);
                mma16816(accE[jp*2+1][mt], ah[mt], b2 + 2);
            }
        }
    }

    __syncthreads();   // all warps done reading smem before attn staging reuse

    // ---- epilogue ----
    const int c0 = tg * 2;
    // value cols
    #pragma unroll
    for (int j = 0; j < 8; j++) {
        int c = wn * 64 + j * 8 + c0;
        float2 b = *(const float2*)(bv + c);
        #pragma unroll
        for (int mt = 0; mt < 2; mt++) {
            #pragma unroll
            for (int hr = 0; hr < 2; hr++) {
                int r = wm * 32 + mt * 16 + gr + hr * 8;
                float2 o = make_float2(accV[j][mt][hr * 2 + 0] + b.x,
                                       accV[j][mt][hr * 2 + 1] + b.y);
                *(float2*)(g_value + (q0 + r) * CCH + c) = o;
            }
        }
    }
    // extra cols (off / attn)
    float* Lst = (float*)(smem + P_AH);   // attn logit staging: [128][32]
    #pragma unroll
    for (int j = 0; j < 6; j++) {
        int ce = 128 + wn * 48 + j * 8 + c0;
        if (ce < 192) {
            float2 b = *(const float2*)(boff + (ce - 128));
            #pragma unroll
            for (int mt = 0; mt < 2; mt++)
                #pragma unroll
                for (int hr = 0; hr < 2; hr++) {
                    int r = wm * 32 + mt * 16 + gr + hr * 8;
                    float2 o = make_float2(accE[j][mt][hr * 2 + 0] + b.x,
                                           accE[j][mt][hr * 2 + 1] + b.y);
                    *(float2*)(g_off + (q0 + r) * 64 + (ce - 128)) = o;
                }
        } else {
            int ca = ce - 192;
            float b0 = battn[ca], b1 = battn[ca + 1];
            #pragma unroll
            for (int mt = 0; mt < 2; mt++)
                #pragma unroll
                for (int hr = 0; hr < 2; hr++) {
                    int r = wm * 32 + mt * 16 + gr + hr * 8;
                    Lst[r * 32 + ca]     = accE[j][mt][hr * 2 + 0] + b0;
                    Lst[r * 32 + ca + 1] = accE[j][mt][hr * 2 + 1] + b1;
                }
        }
    }
    __syncthreads();

    // softmax over P=4 for 128*8 groups
    #pragma unroll
    for (int g = tid; g < 1024; g += 256) {
        int row = g >> 3, h = g & 7;
        float4 l = *(const float4*)(Lst + row * 32 + h * 4);
        float m = fmaxf(fmaxf(l.x, l.y), fmaxf(l.z, l.w));
        float e0 = __expf(l.x - m), e1 = __expf(l.y - m),
              e2 = __expf(l.z - m), e3 = __expf(l.w - m);
        float inv = 1.f / (e0 + e1 + e2 + e3);
        *(float4*)(g_attn + (q0 + row) * 32 + h * 4) =
            make_float4(e0 * inv, e1 * inv, e2 * inv, e3 * inv);
    }
}

// ---------------------------------------------------------------------------
// Kernel 2: bilinear sampling + attention-weighted sum (high occupancy)
// ---------------------------------------------------------------------------
__global__ __launch_bounds__(128) void sample_kernel()
{
    const int lane = threadIdx.x & 31;
    const int qloc = threadIdx.x >> 5;
    const size_t n = (size_t)blockIdx.x * 4 + qloc;
    const int b = (int)(n >> 14);
    const int q = (int)(n & (NQ - 1));
    const int h  = lane >> 2;
    const int dq = lane & 3;

    const float refx = (float)(q & 127) * (1.0f / 127.0f);
    const float refy = (float)(q >> 7)  * (1.0f / 127.0f);

    const float* off  = g_off  + n * 64 + h * 8;
    const float* attn = g_attn + n * 32 + h * 4;
    const float* vb   = g_value + ((size_t)b * NQ) * CCH + h * 16 + dq * 4;

    float4 acc = make_float4(0.f, 0.f, 0.f, 0.f);

    #pragma unroll
    for (int p = 0; p < NP; p++) {
        float ox = off[p * 2 + 0];
        float oy = off[p * 2 + 1];
        float a  = attn[p];
        float x = (refx + ox * (1.0f / 128.0f)) * 128.0f - 0.5f;
        float y = (refy + oy * (1.0f / 128.0f)) * 128.0f - 0.5f;
        float x0f = floorf(x), y0f = floorf(y);
        int x0 = (int)x0f, y0 = (int)y0f;
        float wx = x - x0f, wy = y - y0f;
        float w00 = (1.f - wx) * (1.f - wy) * a;
        float w10 = wx * (1.f - wy) * a;
        float w01 = (1.f - wx) * wy * a;
        float w11 = wx * wy * a;

        bool xv0 = (unsigned)x0       < 128u;
        bool xv1 = (unsigned)(x0 + 1) < 128u;
        bool yv0 = (unsigned)y0       < 128u;
        bool yv1 = (unsigned)(y0 + 1) < 128u;

        if (yv0) {
            const float* rp = vb + (size_t)(y0 * 128) * CCH;
            if (xv0) { float4 v = *(const float4*)(rp + (size_t)x0 * CCH);
                       acc.x += w00 * v.x; acc.y += w00 * v.y; acc.z += w00 * v.z; acc.w += w00 * v.w; }
            if (xv1) { float4 v = *(const float4*)(rp + (size_t)(x0 + 1) * CCH);
                       acc.x += w10 * v.x; acc.y += w10 * v.y; acc.z += w10 * v.z; acc.w += w10 * v.w; }
        }
        if (yv1) {
            const float* rp = vb + (size_t)((y0 + 1) * 128) * CCH;
            if (xv0) { float4 v = *(const float4*)(rp + (size_t)x0 * CCH);
                       acc.x += w01 * v.x; acc.y += w01 * v.y; acc.z += w01 * v.z; acc.w += w01 * v.w; }
            if (xv1) { float4 v = *(const float4*)(rp + (size_t)(x0 + 1) * CCH);
                       acc.x += w11 * v.x; acc.y += w11 * v.y; acc.z += w11 * v.z; acc.w += w11 * v.w; }
        }
    }

    *(float4*)(g_sampled + n * CCH + h * 16 + dq * 4) = acc;
}

// ---------------------------------------------------------------------------
// Kernel 3: out = sampled @ Wout + bout + 2*query. ldmatrix + 3-term bf16 mma.
// ---------------------------------------------------------------------------
#define O_AH   0u
#define O_AL   (O_AH + 128u*RB)
#define O_WH   (O_AL + 128u*RB)
#define O_WL   (O_WH + 128u*RB)
#define OUT_SMEM (O_WL + 128u*RB)   // 139264

__global__ __launch_bounds__(256, 1) void out_kernel(
    const float* __restrict__ bout, const float* __restrict__ query,
    float* __restrict__ out)
{
    extern __shared__ __align__(16) unsigned char smem[];
    const int tid = threadIdx.x;
    const size_t q0 = (size_t)blockIdx.x * 128;

    {
        const float4* asrc = (const float4*)(g_sampled + q0 * CCH);
        #pragma unroll
        for (int it = 0; it < 16; it++) {
            int idx4 = it * 256 + tid;
            float4 v = asrc[idx4];
            int row = idx4 >> 5, k0 = (idx4 & 31) << 2;
            uint2 hi, lo; split4(v, hi, lo);
            *(uint2*)(smem + O_AH + row * RB + k0 * 2) = hi;
            *(uint2*)(smem + O_AL + row * RB + k0 * 2) = lo;
        }
        const uint4* s;
        s = (const uint4*)g_w3_hi;
        #pragma unroll
        for (int it = 0; it < 8; it++) {
            int idx = it * 256 + tid; int row = idx >> 4, seg = idx & 15;
            *(uint4*)(smem + O_WH + row * RB + seg * 16) = s[idx];
        }
        s = (const uint4*)g_w3_lo;
        #pragma unroll
        for (int it = 0; it < 8; it++) {
            int idx = it * 256 + tid; int row = idx >> 4, seg = idx & 15;
            *(uint4*)(smem + O_WL + row * RB + seg * 16) = s[idx];
        }
    }
    __syncthreads();

    const int lane = tid & 31, wid = tid >> 5;
    const int wm = wid & 3, wn = wid >> 2;
    const int gr = lane >> 2, tg = lane & 3;
    const uint32_t sb = smem_u32(smem);

    const uint32_t aoffH = sb + O_AH + (uint32_t)(wm * 32 + (lane & 15)) * RB + ((lane >> 4) << 4);
    const uint32_t aoffL = aoffH + (O_AL - O_AH);
    const uint32_t bRow  = (uint32_t)((lane & 7) + ((lane >> 4 & 1) << 3));
    const uint32_t bCol  = (uint32_t)((lane >> 3 & 1) << 4);
    const uint32_t bhO   = sb + O_WH + (uint32_t)(wn * 64) * RB + bRow * RB + bCol;
    const uint32_t blO   = bhO + (O_WL - O_WH);

    float acc[8][2][4];
    #pragma unroll
    for (int j = 0; j < 8; j++)
        #pragma unroll
        for (int mt = 0; mt < 2; mt++)
            #pragma unroll
            for (int e = 0; e < 4; e++) acc[j][mt][e] = 0.f;

    #pragma unroll
    for (int kc = 0; kc < 8; kc++) {
        const uint32_t kOff = (uint32_t)kc * 32;
        uint32_t ah[2][4], al[2][4];
        ldsm_x4(ah[0], aoffH + kOff);
        ldsm_x4(ah[1], aoffH + 16 * RB + kOff);
        ldsm_x4(al[0], aoffL + kOff);
        ldsm_x4(al[1], aoffL + 16 * RB + kOff);
        #pragma unroll
        for (int jp = 0; jp < 4; jp++) {
            uint32_t bh[4], bl[4];
            ldsm_x4(bh, bhO + (uint32_t)jp * 16 * RB + kOff);
            ldsm_x4(bl, blO + (uint32_t)jp * 16 * RB + kOff);
            #pragma unroll
            for (int mt = 0; mt < 2; mt++) {
                mma16816(acc[jp*2][mt],   ah[mt], bh);
                mma16816(acc[jp*2][mt],   ah[mt], bl);
                mma16816(acc[jp*2][mt],   al[mt], bh);
                mma16816(acc[jp*2+1][mt], ah[mt], bh + 2);
                mma16816(acc[jp*2+1][mt], ah[mt], bl + 2);
                mma16816(acc[jp*2+1][mt], al[mt], bh + 2);
            }
        }
    }

    const int c0 = tg * 2;
    #pragma unroll
    for (int j = 0; j < 8; j++) {
        int c = wn * 64 + j * 8 + c0;
        float2 b = *(const float2*)(bout + c);
        #pragma unroll
        for (int mt = 0; mt < 2; mt++) {
            #pragma unroll
            for (int hr = 0; hr < 2; hr++) {
                int r = wm * 32 + mt * 16 + gr + hr * 8;
                size_t nn = q0 + r;
                float2 qv = *(const float2*)(query + nn * CCH + c);
                float2 o = make_float2(acc[j][mt][hr * 2 + 0] + b.x + 2.0f * qv.x,
                                       acc[j][mt][hr * 2 + 1] + b.y + 2.0f * qv.y);
                *(float2*)(out + nn * CCH + c) = o;
            }
        }
    }
}

// ---------------------------------------------------------------------------
extern "C" void kernel_launch(void* const* d_in, const int* in_sizes, int n_in,
                              void* d_out, int out_size)
{
    const float* query = (const float*)d_in[0];
    const float* Wv    = (const float*)d_in[1];
    const float* bv    = (const float*)d_in[2];
    const float* Woff  = (const float*)d_in[3];
    const float* boff  = (const float*)d_in[4];
    const float* Wattn = (const float*)d_in[5];
    const float* battn = (const float*)d_in[6];
    const float* Wout  = (const float*)d_in[7];
    const float* bout  = (const float*)d_in[8];
    float* out = (float*)d_out;

    cudaFuncSetAttribute(proj_kernel, cudaFuncAttributeMaxDynamicSharedMemorySize, PROJ_SMEM);
    cudaFuncSetAttribute(out_kernel,  cudaFuncAttributeMaxDynamicSharedMemorySize, OUT_SMEM);

    prep_kernel<<<112, 256>>>(Wv, Woff, Wattn, Wout);
    proj_kernel<<<NTOT / 128, 256, PROJ_SMEM>>>(query, bv, boff, battn);
    sample_kernel<<<NTOT / 4, 128>>>();
    out_kernel<<<NTOT / 128, 256, OUT_SMEM>>>(bout, query, out);
}

// round 14
// speedup vs baseline: 2.3409x; 1.1043x over previous
#include <cuda_runtime.h>
#include <cuda_bf16.h>
#include <stdint.h>
#include <math.h>

#define BS   8
#define RES  128
#define NQ   (RES*RES)       // 16384
#define CCH  128
#define NH   8
#define NP   4
#define NTOT (BS*NQ)         // 131072

// ---------------- scratch (device globals; no allocation) -------------------
__device__ __align__(16) __nv_bfloat16 g_value  [(size_t)NTOT*CCH];   // bf16 now
__device__ float g_off    [(size_t)NTOT*64];
__device__ float g_attn   [(size_t)NTOT*32];
__device__ __align__(16) __nv_bfloat16 g_sampled[(size_t)NTOT*CCH];   // bf16 now

// packed transposed bf16 weight images, [n][k] row-major, k contiguous
__device__ __align__(16) __nv_bfloat16 g_w1_hi[128*128];  // Wv^T
__device__ __align__(16) __nv_bfloat16 g_w1_lo[128*128];
__device__ __align__(16) __nv_bfloat16 g_w2_hi[96*128];   // [Woff|Wattn]^T
__device__ __align__(16) __nv_bfloat16 g_w3_hi[128*128];  // Wout^T
__device__ __align__(16) __nv_bfloat16 g_w3_lo[128*128];

// ---------------- helpers ---------------------------------------------------
__device__ __forceinline__ uint32_t smem_u32(const void* p) {
    uint32_t a;
    asm("{ .reg .u64 t; cvta.to.shared.u64 t, %1; cvt.u32.u64 %0, t; }" : "=r"(a) : "l"(p));
    return a;
}
__device__ __forceinline__ uint32_t packbf(float a, float b) {
    uint32_t r;
    asm("cvt.rn.bf16x2.f32 %0, %1, %2;" : "=r"(r) : "f"(b), "f"(a));
    return r;
}
// split float4 (4 consecutive k) into hi/lo bf16x2 pairs
__device__ __forceinline__ void split4(float4 v, uint2& hi, uint2& lo) {
    uint32_t h01 = packbf(v.x, v.y);
    uint32_t h23 = packbf(v.z, v.w);
    float f0 = __uint_as_float(h01 << 16);
    float f1 = __uint_as_float(h01 & 0xffff0000u);
    float f2 = __uint_as_float(h23 << 16);
    float f3 = __uint_as_float(h23 & 0xffff0000u);
    hi = make_uint2(h01, h23);
    lo = make_uint2(packbf(v.x - f0, v.y - f1), packbf(v.z - f2, v.w - f3));
}

// mma.sync m16n8k16 row.col bf16 -> f32 accumulate (in-place)
__device__ __forceinline__ void mma16816(float* c, const uint32_t* a, const uint32_t* b) {
    asm volatile(
        "mma.sync.aligned.m16n8k16.row.col.f32.bf16.bf16.f32 "
        "{%0,%1,%2,%3}, {%4,%5,%6,%7}, {%8,%9}, {%0,%1,%2,%3};"
        : "+f"(c[0]), "+f"(c[1]), "+f"(c[2]), "+f"(c[3])
        : "r"(a[0]), "r"(a[1]), "r"(a[2]), "r"(a[3]), "r"(b[0]), "r"(b[1]));
}

__device__ __forceinline__ void ldsm_x4(uint32_t* r, uint32_t addr) {
    asm volatile("ldmatrix.sync.aligned.m8n8.x4.shared.b16 {%0,%1,%2,%3}, [%4];"
        : "=r"(r[0]), "=r"(r[1]), "=r"(r[2]), "=r"(r[3]) : "r"(addr));
}

#define PSTR 136              // padded bf16 row stride (272 bytes, conflict-free)
#define RB   (PSTR*2u)        // 272

// ---------------------------------------------------------------------------
// prep: transposed, split-bf16 packed weight images
// ---------------------------------------------------------------------------
__global__ void prep_kernel(const float* __restrict__ Wv, const float* __restrict__ Woff,
                            const float* __restrict__ Wattn, const float* __restrict__ Wout)
{
    int i = blockIdx.x * 256 + threadIdx.x;
    if (i < 16384) {
        int k = i >> 7, n = i & 127;
        int o = n * 128 + k;
        {
            float v = Wv[i];
            __nv_bfloat16 h = __float2bfloat16(v);
            g_w1_hi[o] = h;
            g_w1_lo[o] = __float2bfloat16(v - __bfloat162float(h));
        }
        {
            float v = Wout[i];
            __nv_bfloat16 h = __float2bfloat16(v);
            g_w3_hi[o] = h;
            g_w3_lo[o] = __float2bfloat16(v - __bfloat162float(h));
        }
    } else if (i < 16384 + 12288) {
        int j = i - 16384;
        int k = j / 96, n = j - 96 * k;
        float v = (n < 64) ? Woff[k * 64 + n] : Wattn[k * 32 + (n - 64)];
        g_w2_hi[n * 128 + k] = __float2bfloat16(v);
    }
}

// ---------------------------------------------------------------------------
// Kernel 1: proj. CTA tile 128 rows x 224 cols, K=128. 8 warps = 4(M) x 2(N).
// cols 0..127 -> value (3-term, bf16 out), 128..191 -> off, 192..223 -> attn.
// ---------------------------------------------------------------------------
#define P_AH   0u
#define P_AL   (P_AH + 128u*RB)
#define P_WVH  (P_AL + 128u*RB)
#define P_WVL  (P_WVH + 128u*RB)
#define P_W2   (P_WVL + 128u*RB)
#define PROJ_SMEM (P_W2 + 96u*RB)     // 165376

__global__ __launch_bounds__(256, 1) void proj_kernel(
    const float* __restrict__ query,
    const float* __restrict__ bv, const float* __restrict__ boff,
    const float* __restrict__ battn)
{
    extern __shared__ __align__(16) unsigned char smem[];
    const int tid = threadIdx.x;
    const size_t q0 = (size_t)blockIdx.x * 128;

    // ---- stage A: 128x128 fp32 -> hi/lo bf16, padded rows (4096 float4) ----
    {
        const float4* qsrc = (const float4*)(query + q0 * CCH);
        #pragma unroll
        for (int it = 0; it < 16; it++) {
            int idx4 = it * 256 + tid;
            float4 v = qsrc[idx4];
            int row = idx4 >> 5, k0 = (idx4 & 31) << 2;
            uint2 hi, lo; split4(v, hi, lo);
            *(uint2*)(smem + P_AH + row * RB + k0 * 2) = hi;
            *(uint2*)(smem + P_AL + row * RB + k0 * 2) = lo;
        }
    }
    // ---- stage B: copy packed images into padded rows ----
    {
        const uint4* s;
        s = (const uint4*)g_w1_hi;
        #pragma unroll
        for (int it = 0; it < 8; it++) {
            int idx = it * 256 + tid; int row = idx >> 4, seg = idx & 15;
            *(uint4*)(smem + P_WVH + row * RB + seg * 16) = s[idx];
        }
        s = (const uint4*)g_w1_lo;
        #pragma unroll
        for (int it = 0; it < 8; it++) {
            int idx = it * 256 + tid; int row = idx >> 4, seg = idx & 15;
            *(uint4*)(smem + P_WVL + row * RB + seg * 16) = s[idx];
        }
        s = (const uint4*)g_w2_hi;
        #pragma unroll
        for (int it = 0; it < 6; it++) {
            int idx = it * 256 + tid; int row = idx >> 4, seg = idx & 15;
            *(uint4*)(smem + P_W2 + row * RB + seg * 16) = s[idx];
        }
    }
    __syncthreads();

    const int lane = tid & 31, wid = tid >> 5;
    const int wm = wid & 3, wn = wid >> 2;
    const int gr = lane >> 2, tg = lane & 3;
    const uint32_t sb = smem_u32(smem);

    // ldmatrix lane->address precompute
    const uint32_t aoffH = sb + P_AH + (uint32_t)(wm * 32 + (lane & 15)) * RB + ((lane >> 4) << 4);
    const uint32_t aoffL = aoffH + (P_AL - P_AH);
    const uint32_t bRow  = (uint32_t)((lane & 7) + ((lane >> 4 & 1) << 3));
    const uint32_t bCol  = (uint32_t)((lane >> 3 & 1) << 4);
    const uint32_t bvhO  = sb + P_WVH + (uint32_t)(wn * 64) * RB + bRow * RB + bCol;
    const uint32_t bvlO  = bvhO + (P_WVL - P_WVH);
    const uint32_t b2O   = sb + P_W2 + (uint32_t)(wn * 48) * RB + bRow * RB + bCol;

    float accV[8][2][4];
    float accE[6][2][4];
    #pragma unroll
    for (int j = 0; j < 8; j++)
        #pragma unroll
        for (int mt = 0; mt < 2; mt++)
            #pragma unroll
            for (int e = 0; e < 4; e++) accV[j][mt][e] = 0.f;
    #pragma unroll
    for (int j = 0; j < 6; j++)
        #pragma unroll
        for (int mt = 0; mt < 2; mt++)
            #pragma unroll
            for (int e = 0; e < 4; e++) accE[j][mt][e] = 0.f;

    #pragma unroll
    for (int kc = 0; kc < 8; kc++) {
        const uint32_t kOff = (uint32_t)kc * 32;
        uint32_t ah[2][4], al[2][4];
        ldsm_x4(ah[0], aoffH + kOff);
        ldsm_x4(ah[1], aoffH + 16 * RB + kOff);
        ldsm_x4(al[0], aoffL + kOff);
        ldsm_x4(al[1], aoffL + 16 * RB + kOff);
        #pragma unroll
        for (int jp = 0; jp < 4; jp++) {
            uint32_t bh[4], bl[4];
            ldsm_x4(bh, bvhO + (uint32_t)jp * 16 * RB + kOff);
            ldsm_x4(bl, bvlO + (uint32_t)jp * 16 * RB + kOff);
            #pragma unroll
            for (int mt = 0; mt < 2; mt++) {
                mma16816(accV[jp*2][mt],   ah[mt], bh);
                mma16816(accV[jp*2][mt],   ah[mt], bl);
                mma16816(accV[jp*2][mt],   al[mt], bh);
                mma16816(accV[jp*2+1][mt], ah[mt], bh + 2);
                mma16816(accV[jp*2+1][mt], ah[mt], bl + 2);
                mma16816(accV[jp*2+1][mt], al[mt], bh + 2);
            }
        }
        #pragma unroll
        for (int jp = 0; jp < 3; jp++) {
            uint32_t b2[4];
            ldsm_x4(b2, b2O + (uint32_t)jp * 16 * RB + kOff);
            #pragma unroll
            for (int mt = 0; mt < 2; mt++) {
                mma16816(accE[jp*2][mt],   ah[mt], b2);
                mma16816(accE[jp*2+1][mt], ah[mt], b2 + 2);
            }
        }
    }

    __syncthreads();   // all warps done reading smem before attn staging reuse

    // ---- epilogue ----
    const int c0 = tg * 2;
    // value cols -> bf16 packed
    #pragma unroll
    for (int j = 0; j < 8; j++) {
        int c = wn * 64 + j * 8 + c0;
        float2 b = *(const float2*)(bv + c);
        #pragma unroll
        for (int mt = 0; mt < 2; mt++) {
            #pragma unroll
            for (int hr = 0; hr < 2; hr++) {
                int r = wm * 32 + mt * 16 + gr + hr * 8;
                uint32_t pk = packbf(accV[j][mt][hr * 2 + 0] + b.x,
                                     accV[j][mt][hr * 2 + 1] + b.y);
                *(uint32_t*)((unsigned char*)g_value + ((q0 + r) * CCH + c) * 2) = pk;
            }
        }
    }
    // extra cols (off / attn)
    float* Lst = (float*)(smem + P_AH);   // attn logit staging: [128][32]
    #pragma unroll
    for (int j = 0; j < 6; j++) {
        int ce = 128 + wn * 48 + j * 8 + c0;
        if (ce < 192) {
            float2 b = *(const float2*)(boff + (ce - 128));
            #pragma unroll
            for (int mt = 0; mt < 2; mt++)
                #pragma unroll
                for (int hr = 0; hr < 2; hr++) {
                    int r = wm * 32 + mt * 16 + gr + hr * 8;
                    float2 o = make_float2(accE[j][mt][hr * 2 + 0] + b.x,
                                           accE[j][mt][hr * 2 + 1] + b.y);
                    *(float2*)(g_off + (q0 + r) * 64 + (ce - 128)) = o;
                }
        } else {
            int ca = ce - 192;
            float b0 = battn[ca], b1 = battn[ca + 1];
            #pragma unroll
            for (int mt = 0; mt < 2; mt++)
                #pragma unroll
                for (int hr = 0; hr < 2; hr++) {
                    int r = wm * 32 + mt * 16 + gr + hr * 8;
                    Lst[r * 32 + ca]     = accE[j][mt][hr * 2 + 0] + b0;
                    Lst[r * 32 + ca + 1] = accE[j][mt][hr * 2 + 1] + b1;
                }
        }
    }
    __syncthreads();

    // softmax over P=4 for 128*8 groups
    #pragma unroll
    for (int g = tid; g < 1024; g += 256) {
        int row = g >> 3, h = g & 7;
        float4 l = *(const float4*)(Lst + row * 32 + h * 4);
        float m = fmaxf(fmaxf(l.x, l.y), fmaxf(l.z, l.w));
        float e0 = __expf(l.x - m), e1 = __expf(l.y - m),
              e2 = __expf(l.z - m), e3 = __expf(l.w - m);
        float inv = 1.f / (e0 + e1 + e2 + e3);
        *(float4*)(g_attn + (q0 + row) * 32 + h * 4) =
            make_float4(e0 * inv, e1 * inv, e2 * inv, e3 * inv);
    }
}

// ---------------------------------------------------------------------------
// Kernel 2: bilinear sampling (bf16 value in, bf16 sampled out, fp32 math)
// ---------------------------------------------------------------------------
__device__ __forceinline__ void acc_tap(float4& acc, const __nv_bfloat16* p, float w) {
    uint2 v = *(const uint2*)p;
    acc.x += w * __uint_as_float(v.x << 16);
    acc.y += w * __uint_as_float(v.x & 0xffff0000u);
    acc.z += w * __uint_as_float(v.y << 16);
    acc.w += w * __uint_as_float(v.y & 0xffff0000u);
}

__global__ __launch_bounds__(128) void sample_kernel()
{
    const int lane = threadIdx.x & 31;
    const int qloc = threadIdx.x >> 5;
    const size_t n = (size_t)blockIdx.x * 4 + qloc;
    const int b = (int)(n >> 14);
    const int q = (int)(n & (NQ - 1));
    const int h  = lane >> 2;
    const int dq = lane & 3;

    const float refx = (float)(q & 127) * (1.0f / 127.0f);
    const float refy = (float)(q >> 7)  * (1.0f / 127.0f);

    const float* off  = g_off  + n * 64 + h * 8;
    const float* attn = g_attn + n * 32 + h * 4;
    const __nv_bfloat16* vb = g_value + ((size_t)b * NQ) * CCH + h * 16 + dq * 4;

    float4 acc = make_float4(0.f, 0.f, 0.f, 0.f);

    #pragma unroll
    for (int p = 0; p < NP; p++) {
        float ox = off[p * 2 + 0];
        float oy = off[p * 2 + 1];
        float a  = attn[p];
        float x = (refx + ox * (1.0f / 128.0f)) * 128.0f - 0.5f;
        float y = (refy + oy * (1.0f / 128.0f)) * 128.0f - 0.5f;
        float x0f = floorf(x), y0f = floorf(y);
        int x0 = (int)x0f, y0 = (int)y0f;
        float wx = x - x0f, wy = y - y0f;
        float w00 = (1.f - wx) * (1.f - wy) * a;
        float w10 = wx * (1.f - wy) * a;
        float w01 = (1.f - wx) * wy * a;
        float w11 = wx * wy * a;

        bool xv0 = (unsigned)x0       < 128u;
        bool xv1 = (unsigned)(x0 + 1) < 128u;
        bool yv0 = (unsigned)y0       < 128u;
        bool yv1 = (unsigned)(y0 + 1) < 128u;

        if (yv0) {
            const __nv_bfloat16* rp = vb + (size_t)(y0 * 128) * CCH;
            if (xv0) acc_tap(acc, rp + (size_t)x0 * CCH, w00);
            if (xv1) acc_tap(acc, rp + (size_t)(x0 + 1) * CCH, w10);
        }
        if (yv1) {
            const __nv_bfloat16* rp = vb + (size_t)((y0 + 1) * 128) * CCH;
            if (xv0) acc_tap(acc, rp + (size_t)x0 * CCH, w01);
            if (xv1) acc_tap(acc, rp + (size_t)(x0 + 1) * CCH, w11);
        }
    }

    uint2 pk = make_uint2(packbf(acc.x, acc.y), packbf(acc.z, acc.w));
    *(uint2*)(g_sampled + n * CCH + h * 16 + dq * 4) = pk;
}

// ---------------------------------------------------------------------------
// Kernel 3: out = sampled(bf16) @ Wout + bout + 2*query. 2-term, 2 CTAs/SM.
// ---------------------------------------------------------------------------
#define O_A    0u
#define O_WH   (O_A  + 128u*RB)
#define O_WL   (O_WH + 128u*RB)
#define OUT_SMEM (O_WL + 128u*RB)   // 104448

__global__ __launch_bounds__(256, 2) void out_kernel(
    const float* __restrict__ bout, const float* __restrict__ query,
    float* __restrict__ out)
{
    extern __shared__ __align__(16) unsigned char smem[];
    const int tid = threadIdx.x;
    const size_t q0 = (size_t)blockIdx.x * 128;

    {   // A: direct bf16 copy (128 rows x 256B = 2048 uint4)
        const uint4* s = (const uint4*)(g_sampled + q0 * CCH);
        #pragma unroll
        for (int it = 0; it < 8; it++) {
            int idx = it * 256 + tid; int row = idx >> 4, seg = idx & 15;
            *(uint4*)(smem + O_A + row * RB + seg * 16) = s[idx];
        }
        const uint4* w;
        w = (const uint4*)g_w3_hi;
        #pragma unroll
        for (int it = 0; it < 8; it++) {
            int idx = it * 256 + tid; int row = idx >> 4, seg = idx & 15;
            *(uint4*)(smem + O_WH + row * RB + seg * 16) = w[idx];
        }
        w = (const uint4*)g_w3_lo;
        #pragma unroll
        for (int it = 0; it < 8; it++) {
            int idx = it * 256 + tid; int row = idx >> 4, seg = idx & 15;
            *(uint4*)(smem + O_WL + row * RB + seg * 16) = w[idx];
        }
    }
    __syncthreads();

    const int lane = tid & 31, wid = tid >> 5;
    const int wm = wid & 3, wn = wid >> 2;
    const int gr = lane >> 2, tg = lane & 3;
    const uint32_t sb = smem_u32(smem);

    const uint32_t aoff = sb + O_A + (uint32_t)(wm * 32 + (lane & 15)) * RB + ((lane >> 4) << 4);
    const uint32_t bRow = (uint32_t)((lane & 7) + ((lane >> 4 & 1) << 3));
    const uint32_t bCol = (uint32_t)((lane >> 3 & 1) << 4);
    const uint32_t bhO  = sb + O_WH + (uint32_t)(wn * 64) * RB + bRow * RB + bCol;
    const uint32_t blO  = bhO + (O_WL - O_WH);

    float acc[8][2][4];
    #pragma unroll
    for (int j = 0; j < 8; j++)
        #pragma unroll
        for (int mt = 0; mt < 2; mt++)
            #pragma unroll
            for (int e = 0; e < 4; e++) acc[j][mt][e] = 0.f;

    #pragma unroll
    for (int kc = 0; kc < 8; kc++) {
        const uint32_t kOff = (uint32_t)kc * 32;
        uint32_t ah[2][4];
        ldsm_x4(ah[0], aoff + kOff);
        ldsm_x4(ah[1], aoff + 16 * RB + kOff);
        #pragma unroll
        for (int jp = 0; jp < 4; jp++) {
            uint32_t bh[4], bl[4];
            ldsm_x4(bh, bhO + (uint32_t)jp * 16 * RB + kOff);
            ldsm_x4(bl, blO + (uint32_t)jp * 16 * RB + kOff);
            #pragma unroll
            for (int mt = 0; mt < 2; mt++) {
                mma16816(acc[jp*2][mt],   ah[mt], bh);
                mma16816(acc[jp*2][mt],   ah[mt], bl);
                mma16816(acc[jp*2+1][mt], ah[mt], bh + 2);
                mma16816(acc[jp*2+1][mt], ah[mt], bl + 2);
            }
        }
    }

    const int c0 = tg * 2;
    #pragma unroll
    for (int j = 0; j < 8; j++) {
        int c = wn * 64 + j * 8 + c0;
        float2 b = *(const float2*)(bout + c);
        #pragma unroll
        for (int mt = 0; mt < 2; mt++) {
            #pragma unroll
            for (int hr = 0; hr < 2; hr++) {
                int r = wm * 32 + mt * 16 + gr + hr * 8;
                size_t nn = q0 + r;
                float2 qv = *(const float2*)(query + nn * CCH + c);
                float2 o = make_float2(acc[j][mt][hr * 2 + 0] + b.x + 2.0f * qv.x,
                                       acc[j][mt][hr * 2 + 1] + b.y + 2.0f * qv.y);
                *(float2*)(out + nn * CCH + c) = o;
            }
        }
    }
}

// ---------------------------------------------------------------------------
extern "C" void kernel_launch(void* const* d_in, const int* in_sizes, int n_in,
                              void* d_out, int out_size)
{
    const float* query = (const float*)d_in[0];
    const float* Wv    = (const float*)d_in[1];
    const float* bv    = (const float*)d_in[2];
    const float* Woff  = (const float*)d_in[3];
    const float* boff  = (const float*)d_in[4];
    const float* Wattn = (const float*)d_in[5];
    const float* battn = (const float*)d_in[6];
    const float* Wout  = (const float*)d_in[7];
    const float* bout  = (const float*)d_in[8];
    float* out = (float*)d_out;

    cudaFuncSetAttribute(proj_kernel, cudaFuncAttributeMaxDynamicSharedMemorySize, PROJ_SMEM);
    cudaFuncSetAttribute(out_kernel,  cudaFuncAttributeMaxDynamicSharedMemorySize, OUT_SMEM);

    prep_kernel<<<112, 256>>>(Wv, Woff, Wattn, Wout);
    proj_kernel<<<NTOT / 128, 256, PROJ_SMEM>>>(query, bv, boff, battn);
    sample_kernel<<<NTOT / 4, 128>>>();
    out_kernel<<<NTOT / 128, 256, OUT_SMEM>>>(bout, query, out);
}